// round 10
// baseline (speedup 1.0000x reference)
#include <cuda_runtime.h>
#include <cuda_bf16.h>
#include <cstdint>

#define BB 8
#define NN 4096
#define CC 64
#define OUTC 64
#define NS 32
#define R2C 0.04f
#define ALPHA 0.2f
#define CAPK 224
#define NCELL 1000
// full float bits of 0.0225f (= 0.15^2), exact tight threshold on the d2 word
#define TIGHT32 0x3CB850EBu
#define TIGHTKEY64 ((unsigned long long)TIGHT32 << 32)

// ---- device scratch (allocation-free rule) ----
__device__ uint32_t g_featTbW[(size_t)BB * NN * 64];            // per row: 64 words, word 2w={bf16 hi pair w}, 2w+1={lo pair w}
__device__ __nv_bfloat16 g_projLb[(size_t)BB * NN * 2048];      // per row: hi[1024], lo[1024]
__device__ __nv_bfloat16 g_WcPb[(size_t)OUTC * 2048];           // per row: hi[1024], lo[1024]
__device__ int   g_idx[(size_t)BB * NN * NS];
__device__ float g_gx [(size_t)BB * NN * NS];
__device__ float g_gy [(size_t)BB * NN * NS];
__device__ float g_gz [(size_t)BB * NN * NS];
__device__ float4 g_pts4[(size_t)BB * NN];                      // cell-sorted {x,y,z,origIdx}
__device__ int   g_cellStart[(size_t)BB * (NCELL + 1)];

__device__ __forceinline__ float leaky(float x) { return fmaxf(x, ALPHA * x); }

__device__ __forceinline__ uint32_t pack_hi(float v0, float v1, float& r0, float& r1) {
    __nv_bfloat16 h0 = __float2bfloat16_rn(v0);
    __nv_bfloat16 h1 = __float2bfloat16_rn(v1);
    r0 = v0 - __bfloat162float(h0);
    r1 = v1 - __bfloat162float(h1);
    uint16_t u0 = *(uint16_t*)&h0, u1 = *(uint16_t*)&h1;
    return ((uint32_t)u1 << 16) | u0;
}
__device__ __forceinline__ uint32_t pack_bf2(float v0, float v1) {
    __nv_bfloat16 h0 = __float2bfloat16_rn(v0);
    __nv_bfloat16 h1 = __float2bfloat16_rn(v1);
    uint16_t u0 = *(uint16_t*)&h0, u1 = *(uint16_t*)&h1;
    return ((uint32_t)u1 << 16) | u0;
}

__device__ __forceinline__ void mma_bf16(float* c, const uint32_t* a, const uint32_t* b) {
    asm volatile(
        "mma.sync.aligned.m16n8k16.row.col.f32.bf16.bf16.f32 "
        "{%0,%1,%2,%3}, {%4,%5,%6,%7}, {%8,%9}, {%0,%1,%2,%3};"
        : "+f"(c[0]), "+f"(c[1]), "+f"(c[2]), "+f"(c[3])
        : "r"(a[0]), "r"(a[1]), "r"(a[2]), "r"(a[3]), "r"(b[0]), "r"(b[1]));
}

__device__ __forceinline__ void ldmx2t(uint32_t& r0, uint32_t& r1, uint32_t saddr) {
    asm volatile("ldmatrix.sync.aligned.m8n8.x2.trans.shared.b16 {%0,%1}, [%2];"
                 : "=r"(r0), "=r"(r1) : "r"(saddr));
}
__device__ __forceinline__ uint32_t smem_u32(const void* p) {
    return (uint32_t)__cvta_generic_to_shared(p);
}

// ---------------- transpose + bf16 hi/lo split: (B,C,N) fp32 -> (B,N) rows of {hi,lo} pair-words ----------------
__global__ void transpose_kernel(const float* __restrict__ feat) {
    __shared__ float tile[32][33];
    int b = blockIdx.z, n0 = blockIdx.x * 32, c0 = blockIdx.y * 32;
    int tx = threadIdx.x, ty = threadIdx.y;
    const float* fb = feat + (size_t)b * CC * NN;
    uint32_t* ob = g_featTbW + (size_t)b * NN * 64;
#pragma unroll
    for (int i = 0; i < 4; i++)
        tile[ty + i * 8][tx] = fb[(size_t)(c0 + ty + i * 8) * NN + n0 + tx];
    __syncthreads();
    if (tx < 16) {
#pragma unroll
        for (int i = 0; i < 4; i++) {
            int n = n0 + ty + i * 8;
            float f0 = tile[2 * tx][ty + i * 8];
            float f1 = tile[2 * tx + 1][ty + i * 8];
            float r0, r1;
            uint32_t hw = pack_hi(f0, f1, r0, r1);
            uint32_t lw = pack_bf2(r0, r1);
            uint2 v; v.x = hw; v.y = lw;
            *(uint2*)(ob + (size_t)n * 64 + (c0 / 2 + tx) * 2) = v;
        }
    }
}

// ---------------- Wc permute + bf16 split ----------------
__global__ void wcperm_kernel(const float* __restrict__ Wc) {
    int idx = blockIdx.x * 256 + threadIdx.x;   // 32768 pairs
    int o = idx >> 9, pair = idx & 511;
    int kc0 = pair * 2;
    int c = kc0 & 63, k = kc0 >> 6;
    float x0 = Wc[o * 1024 + c * 16 + k];
    float x1 = Wc[o * 1024 + (c + 1) * 16 + k];
    float r0, r1;
    uint32_t hw = pack_hi(x0, x1, r0, r1);
    uint32_t lw = pack_bf2(r0, r1);
    uint32_t* row = (uint32_t*)(g_WcPb + (size_t)o * 2048);
    row[pair] = hw;
    row[512 + pair] = lw;
}

// ---------------- bin: counting sort into 10^3 cells ----------------
__global__ __launch_bounds__(1024) void bin_kernel(const float* __restrict__ xyz) {
    __shared__ int cnt[NCELL];
    __shared__ int off[NCELL];
    __shared__ int wsum[32];
    int b = blockIdx.x, tid = threadIdx.x, lane = tid & 31, wid = tid >> 5;
    for (int i = tid; i < NCELL; i += 1024) cnt[i] = 0;
    __syncthreads();

    float xs[4], ys[4], zs[4];
    int cell[4];
    const float* xb = xyz + (size_t)b * NN * 3;
#pragma unroll
    for (int t = 0; t < 4; t++) {
        int n = tid * 4 + t;
        xs[t] = xb[n * 3 + 0];
        ys[t] = xb[n * 3 + 1];
        zs[t] = xb[n * 3 + 2];
        int ci = min((int)(xs[t] * 10.f), 9);
        int cj = min((int)(ys[t] * 10.f), 9);
        int ck = min((int)(zs[t] * 10.f), 9);
        cell[t] = (ck * 10 + cj) * 10 + ci;
        atomicAdd(&cnt[cell[t]], 1);
    }
    __syncthreads();

    int v = (tid < NCELL) ? cnt[tid] : 0;
    int orig = v;
#pragma unroll
    for (int d = 1; d < 32; d <<= 1) {
        int t2 = __shfl_up_sync(0xffffffffu, v, d);
        if (lane >= d) v += t2;
    }
    if (lane == 31) wsum[wid] = v;
    __syncthreads();
    if (wid == 0) {
        int s = wsum[lane];
#pragma unroll
        for (int d = 1; d < 32; d <<= 1) {
            int t2 = __shfl_up_sync(0xffffffffu, s, d);
            if (lane >= d) s += t2;
        }
        wsum[lane] = s;
    }
    __syncthreads();
    int excl = v + (wid > 0 ? wsum[wid - 1] : 0) - orig;
    if (tid < NCELL) {
        off[tid] = excl;
        g_cellStart[(size_t)b * (NCELL + 1) + tid] = excl;
    }
    if (tid == 0) g_cellStart[(size_t)b * (NCELL + 1) + NCELL] = NN;
    __syncthreads();

#pragma unroll
    for (int t = 0; t < 4; t++) {
        int n = tid * 4 + t;
        int pos = atomicAdd(&off[cell[t]], 1);
        g_pts4[(size_t)b * NN + pos] = make_float4(xs[t], ys[t], zs[t], __int_as_float(n));
    }
}

// ---------------- KNN: sorted-center shared scan + tight-filtered rank selection ----------------
#define KNN_SMEM (size_t)(8 * 4 * CAPK * 8 + (NCELL + 8) * 4 + 32 * 4)

#define RANK_LOOP(cd, Mlen, kk, rr)                                         \
    do {                                                                    \
        if ((Mlen) <= 64) {                                                 \
            for (int q = 0; q < (Mlen); q++) {                              \
                unsigned long long kq = (cd)[q];                            \
                rr[0] += (kq < kk[0]); rr[1] += (kq < kk[1]);               \
            }                                                               \
        } else if ((Mlen) <= 128) {                                         \
            for (int q = 0; q < (Mlen); q++) {                              \
                unsigned long long kq = (cd)[q];                            \
                rr[0] += (kq < kk[0]); rr[1] += (kq < kk[1]);               \
                rr[2] += (kq < kk[2]); rr[3] += (kq < kk[3]);               \
            }                                                               \
        } else {                                                            \
            for (int q = 0; q < (Mlen); q++) {                              \
                unsigned long long kq = (cd)[q];                            \
                rr[0] += (kq < kk[0]); rr[1] += (kq < kk[1]);               \
                rr[2] += (kq < kk[2]); rr[3] += (kq < kk[3]);               \
                rr[4] += (kq < kk[4]); rr[5] += (kq < kk[5]);               \
                rr[6] += (kq < kk[6]);                                      \
            }                                                               \
        }                                                                   \
    } while (0)

__global__ __launch_bounds__(256, 3) void knn_kernel() {
    extern __shared__ char smem_raw[];
    unsigned long long* candAll = (unsigned long long*)smem_raw;
    int* scell = (int*)(candAll + 8 * 4 * CAPK);
    int* scnt = scell + (NCELL + 8);

    int b = blockIdx.y, tid = threadIdx.x, w = tid >> 5, lane = tid & 31;
    const int* cs = g_cellStart + (size_t)b * (NCELL + 1);
    for (int i = tid; i < NCELL + 1; i += 256) scell[i] = cs[i];
    if (tid < 32) scnt[tid] = 0;
    __syncthreads();

    int nbase = blockIdx.x * 32 + w * 4;       // sorted position base
    unsigned long long* cand0 = candAll + (size_t)w * 4 * CAPK;
    int* mycnt = scnt + w * 4;
    const float4* pts = g_pts4 + (size_t)b * NN;

    float cx[4], cy[4], cz[4];
    int oidx[4];
#pragma unroll
    for (int i = 0; i < 4; i++) {
        float4 c = pts[nbase + i];
        cx[i] = c.x; cy[i] = c.y; cz[i] = c.z;
        oidx[i] = __float_as_int(c.w);
    }

    int xlo = 9, xhi = 0, ylo = 9, yhi = 0, zlo = 9, zhi = 0;
#pragma unroll
    for (int i = 0; i < 4; i++) {
        int cxi = min((int)(cx[i] * 10.f), 9);
        int cyi = min((int)(cy[i] * 10.f), 9);
        int czi = min((int)(cz[i] * 10.f), 9);
        xlo = min(xlo, max(cxi - 2, 0)); xhi = max(xhi, min(cxi + 2, 9));
        ylo = min(ylo, max(cyi - 2, 0)); yhi = max(yhi, min(cyi + 2, 9));
        zlo = min(zlo, max(czi - 2, 0)); zhi = max(zhi, min(czi + 2, 9));
    }

    for (int zz = zlo; zz <= zhi; zz++) {
        for (int yy = ylo; yy <= yhi; yy++) {
            int rb = (zz * 10 + yy) * 10;
            int s = scell[rb + xlo], e = scell[rb + xhi + 1];
            for (int p = s + lane; p < e; p += 32) {
                float4 pt = pts[p];
                unsigned lowbase = ((unsigned)__float_as_int(pt.w) << 12) | (unsigned)p;
#pragma unroll
                for (int i = 0; i < 4; i++) {
                    float dx = pt.x - cx[i], dy = pt.y - cy[i], dz = pt.z - cz[i];
                    float d2 = fmaf(dx, dx, fmaf(dy, dy, dz * dz));
                    if (d2 <= R2C) {
                        int pos = atomicAdd(&mycnt[i], 1);
                        if (pos < CAPK)
                            cand0[i * CAPK + pos] =
                                ((unsigned long long)__float_as_uint(d2) << 32) | lowbase;
                    }
                }
            }
        }
    }
    __syncwarp();

#pragma unroll
    for (int i = 0; i < 4; i++) {
        size_t cg = (size_t)b * NN + oidx[i];
        int M = min(mycnt[i], CAPK);
        unsigned long long* cd = cand0 + i * CAPK;
        unsigned lmask = (1u << lane) - 1u;

        if (lane >= M) {
            g_idx[cg * NS + lane] = oidx[i];
            g_gx[cg * NS + lane] = 0.0f;
            g_gy[cg * NS + lane] = 0.0f;
            g_gz[cg * NS + lane] = 0.0f;
        }

        unsigned long long k[7];
#pragma unroll
        for (int t = 0; t < 7; t++) {
            int p = lane + 32 * t;
            k[t] = (p < M) ? cd[p] : ~0ull;
        }
        unsigned bms[7];
        int Mt = 0;
#pragma unroll
        for (int t = 0; t < 7; t++) {
            bms[t] = __ballot_sync(0xffffffffu, k[t] < TIGHTKEY64);
            Mt += __popc(bms[t]);
        }

        if (Mt >= NS) {
            int base = 0;
#pragma unroll
            for (int t = 0; t < 7; t++) {
                if (k[t] < TIGHTKEY64)
                    cd[base + __popc(bms[t] & lmask)] = k[t];
                base += __popc(bms[t]);
            }
            __syncwarp();
            unsigned long long k2[7];
            int rr[7];
#pragma unroll
            for (int t = 0; t < 7; t++) {
                int p = lane + 32 * t;
                k2[t] = (p < Mt) ? cd[p] : ~0ull;
                rr[t] = 0;
            }
            RANK_LOOP(cd, Mt, k2, rr);
#pragma unroll
            for (int t = 0; t < 7; t++) {
                int p = lane + 32 * t;
                if (p < Mt && rr[t] < NS) {
                    int low = (int)(k2[t] & 0xffffffffull);
                    int jj = (low >> 12) & 0xFFF;
                    float4 p4 = pts[low & 0xFFF];
                    g_idx[cg * NS + rr[t]] = jj;
                    g_gx[cg * NS + rr[t]] = p4.x - cx[i];
                    g_gy[cg * NS + rr[t]] = p4.y - cy[i];
                    g_gz[cg * NS + rr[t]] = p4.z - cz[i];
                }
            }
        } else {
            int rr[7];
#pragma unroll
            for (int t = 0; t < 7; t++) rr[t] = 0;
            RANK_LOOP(cd, M, k, rr);
#pragma unroll
            for (int t = 0; t < 7; t++) {
                int p = lane + 32 * t;
                if (p < M && rr[t] < NS) {
                    int low = (int)(k[t] & 0xffffffffull);
                    int jj = (low >> 12) & 0xFFF;
                    float4 p4 = pts[low & 0xFFF];
                    g_idx[cg * NS + rr[t]] = jj;
                    g_gx[cg * NS + rr[t]] = p4.x - cx[i];
                    g_gy[cg * NS + rr[t]] = p4.y - cy[i];
                    g_gz[cg * NS + rr[t]] = p4.z - cz[i];
                }
            }
        }
        __syncwarp();
    }
}

// ---------------- projgen: MLP + normalize + TENSORIZED proj (m16n8k16 bf16 hi/lo) ----------------
#define PJW 4   // warps per block (128 threads)
#define CW 2    // centers per warp
__global__ __launch_bounds__(128) void projgen_kernel(
    const float* __restrict__ W1, const float* __restrict__ b1,
    const float* __restrict__ W2, const float* __restrict__ b2,
    const float* __restrict__ W3, const float* __restrict__ b3)
{
    __shared__ float sW[448];
    __shared__ __align__(16) uint16_t sWh[PJW][512];      // [k][s] halves
    __shared__ __align__(16) uint16_t sWl[PJW][512];
    __shared__ __align__(16) uint16_t sFh[PJW][32 * 40];  // [s][c-half] halves, stride 40
    __shared__ __align__(16) uint16_t sFl[PJW][32 * 40];
    __shared__ int snjAll[PJW][32];

    int tid = threadIdx.x, w = tid >> 5, lane = tid & 31;
    if (tid < 24)  sW[tid] = W1[tid];
    if (tid < 8)   sW[24 + tid] = b1[tid];
    sW[32 + tid]  = W2[tid];            // 128 entries, 128 threads
    if (tid < 16)  sW[160 + tid] = b2[tid];
    sW[176 + tid] = W3[tid];
    sW[304 + tid] = W3[128 + tid];
    if (tid < 16)  sW[432 + tid] = b3[tid];
    __syncthreads();

    uint32_t* Wh = (uint32_t*)sWh[w];
    uint32_t* Wl = (uint32_t*)sWl[w];
    uint32_t* Fh = (uint32_t*)sFh[w];
    uint32_t* Fl = (uint32_t*)sFl[w];
    int* snj = snjAll[w];

    for (int it = 0; it < CW; it++) {
        size_t cg = (size_t)blockIdx.x * (PJW * CW) + w * CW + it;
        int bb = (int)(cg >> 12);

        int   nj = g_idx[cg * NS + lane];
        float gx = g_gx[cg * NS + lane];
        float gy = g_gy[cg * NS + lane];
        float gz = g_gz[cg * NS + lane];

        // MLP 3->8->16->16
        float h1[8];
#pragma unroll
        for (int o = 0; o < 8; o++)
            h1[o] = leaky(fmaf(sW[o*3+0], gx, fmaf(sW[o*3+1], gy, fmaf(sW[o*3+2], gz, sW[24+o]))));
        float h2[16];
#pragma unroll
        for (int o = 0; o < 16; o++) {
            float a = sW[160 + o];
#pragma unroll
            for (int i = 0; i < 8; i++) a = fmaf(sW[32 + o*8 + i], h1[i], a);
            h2[o] = leaky(a);
        }
        float wv[16], w2sum = 0.0f;
#pragma unroll
        for (int o = 0; o < 16; o++) {
            float a = sW[432 + o];
#pragma unroll
            for (int i = 0; i < 16; i++) a = fmaf(sW[176 + o*16 + i], h2[i], a);
            wv[o] = a; w2sum = fmaf(a, a, w2sum);
        }
        float inv1 = rsqrtf(fmaxf(w2sum, 1e-8f));

        // normalize + bf16 split, store transposed [k][s]
#pragma unroll
        for (int kk = 0; kk < 16; kk++) {
            float t = wv[kk] * wv[kk];
#pragma unroll
            for (int off = 16; off; off >>= 1) t += __shfl_xor_sync(0xffffffffu, t, off);
            float s2 = fmaxf(sqrtf(fmaxf(t, 1e-8f)), 1.0f);
            float wn = wv[kk] * inv1 * (1.0f / s2);
            __nv_bfloat16 hb = __float2bfloat16_rn(wn);
            float rr = wn - __bfloat162float(hb);
            __nv_bfloat16 lb = __float2bfloat16_rn(rr);
            sWh[w][kk * 32 + lane] = *(uint16_t*)&hb;
            sWl[w][kk * 32 + lane] = *(uint16_t*)&lb;
        }
        snj[lane] = nj;
        __syncwarp();

        // A fragments (w^T), held in regs across both passes
        uint32_t awh[2][4], awl[2][4];
#pragma unroll
        for (int t = 0; t < 2; t++) {
            int r0 = (lane >> 2), c0 = (lane & 3) + 8 * t;
            awh[t][0] = Wh[r0 * 16 + c0];        awh[t][1] = Wh[(r0 + 8) * 16 + c0];
            awh[t][2] = Wh[r0 * 16 + c0 + 4];    awh[t][3] = Wh[(r0 + 8) * 16 + c0 + 4];
            awl[t][0] = Wl[r0 * 16 + c0];        awl[t][1] = Wl[(r0 + 8) * 16 + c0];
            awl[t][2] = Wl[r0 * 16 + c0 + 4];    awl[t][3] = Wl[(r0 + 8) * 16 + c0 + 4];
        }

        const uint32_t* ftb = g_featTbW + (size_t)bb * NN * 64;
        uint32_t* row = (uint32_t*)(g_projLb + cg * 2048);

#pragma unroll
        for (int pass = 0; pass < 2; pass++) {
            if (pass) __syncwarp();
            // stage 32-channel half: [s][c] bf16 hi/lo, stride 40 halves
            int cp = (lane & 15) + pass * 16;    // global c-pair
#pragma unroll
            for (int r = 0; r < 16; r++) {
                int s = 2 * r + (lane >> 4);
                uint2 v = *(const uint2*)(ftb + (size_t)snj[s] * 64 + 2 * cp);
                Fh[s * 20 + (lane & 15)] = v.x;
                Fl[s * 20 + (lane & 15)] = v.y;
            }
            __syncwarp();

#pragma unroll
            for (int nt = 0; nt < 4; nt++) {
                float acc[4] = {0.f, 0.f, 0.f, 0.f};
                uint32_t bh[2][2], bl[2][2];
#pragma unroll
                for (int t = 0; t < 2; t++) {
                    int s = 16 * t + (lane & 15);
                    uint32_t ah_ = smem_u32(&sFh[w][s * 40 + nt * 8]);
                    ldmx2t(bh[t][0], bh[t][1], ah_);
                    uint32_t al_ = smem_u32(&sFl[w][s * 40 + nt * 8]);
                    ldmx2t(bl[t][0], bl[t][1], al_);
                }
#pragma unroll
                for (int t = 0; t < 2; t++) {
                    mma_bf16(acc, awh[t], bh[t]);
                    mma_bf16(acc, awh[t], bl[t]);
                    mma_bf16(acc, awl[t], bh[t]);
                }
                // epilogue: leaky + bf16 split -> projLb (word = k*32 + c/2)
                int w0 = (lane >> 2) * 32 + pass * 16 + nt * 4 + (lane & 3);
                float v0 = leaky(acc[0]), v1 = leaky(acc[1]);
                float r0, r1;
                uint32_t hw = pack_hi(v0, v1, r0, r1);
                uint32_t lw = pack_bf2(r0, r1);
                row[w0] = hw; row[512 + w0] = lw;
                int w1 = w0 + 8 * 32;
                v0 = leaky(acc[2]); v1 = leaky(acc[3]);
                hw = pack_hi(v0, v1, r0, r1);
                lw = pack_bf2(r0, r1);
                row[w1] = hw; row[512 + w1] = lw;
            }
        }
        __syncwarp();
    }
}

// ---------------- GEMM (bf16 hi/lo split, m16n8k16) ----------------
#define AW (128 * 20)
#define BW (64 * 20)
#define STGW (2 * AW + 2 * BW)
#define GEMM_SMEM_BYTES (2 * STGW * 4)

__global__ __launch_bounds__(256) void gemm_bf16_kernel(
    const float* __restrict__ bc, float* __restrict__ out)
{
    extern __shared__ uint32_t smw[];
    int tid = threadIdx.x, lane = tid & 31, w = tid >> 5;
    size_t row0 = (size_t)blockIdx.x * 128;
    int b = (int)(row0 >> 12), n0 = (int)(row0 & 4095);

    int ar = tid >> 1, ahalf = tid & 1;
    int br = tid >> 2, bq = tid & 3;

    const uint32_t* rowA = (const uint32_t*)(g_projLb + (row0 + ar) * 2048);
    const uint32_t* rowB = (const uint32_t*)(g_WcPb + (size_t)br * 2048);

    int wi = (w & 3) * 32;
    int wj = (w >> 2) * 32;

    float acc[2][4][4];
#pragma unroll
    for (int i = 0; i < 2; i++)
#pragma unroll
        for (int j = 0; j < 4; j++)
#pragma unroll
            for (int q = 0; q < 4; q++) acc[i][j][q] = 0.0f;

    uint4 aH0, aH1, aL0, aL1, bH, bL;
    {
        const uint4* pAh = (const uint4*)(rowA + ahalf * 8);
        const uint4* pAl = (const uint4*)(rowA + 512 + ahalf * 8);
        aH0 = pAh[0]; aH1 = pAh[1]; aL0 = pAl[0]; aL1 = pAl[1];
        bH = *(const uint4*)(rowB + bq * 4);
        bL = *(const uint4*)(rowB + 512 + bq * 4);
    }
    {
        uint32_t* buf = smw;
        *(uint4*)(buf + ar * 20 + ahalf * 8)          = aH0;
        *(uint4*)(buf + ar * 20 + ahalf * 8 + 4)      = aH1;
        *(uint4*)(buf + AW + ar * 20 + ahalf * 8)     = aL0;
        *(uint4*)(buf + AW + ar * 20 + ahalf * 8 + 4) = aL1;
        *(uint4*)(buf + 2 * AW + br * 20 + bq * 4)          = bH;
        *(uint4*)(buf + 2 * AW + BW + br * 20 + bq * 4)     = bL;
    }
    __syncthreads();

    for (int s = 0; s < 32; s++) {
        if (s + 1 < 32) {
            int wb = (s + 1) * 16;
            const uint4* pAh = (const uint4*)(rowA + wb + ahalf * 8);
            const uint4* pAl = (const uint4*)(rowA + 512 + wb + ahalf * 8);
            aH0 = pAh[0]; aH1 = pAh[1]; aL0 = pAl[0]; aL1 = pAl[1];
            bH = *(const uint4*)(rowB + wb + bq * 4);
            bL = *(const uint4*)(rowB + 512 + wb + bq * 4);
        }
        const uint32_t* buf = smw + (s & 1) * STGW;
        const uint32_t* Ah = buf;
        const uint32_t* Al = buf + AW;
        const uint32_t* Bh = buf + 2 * AW;
        const uint32_t* Bl = buf + 2 * AW + BW;

#pragma unroll
        for (int t = 0; t < 2; t++) {
            int wb = t * 8;
            uint32_t ah[2][4], al[2][4];
#pragma unroll
            for (int ii = 0; ii < 2; ii++) {
                int r = wi + ii * 16 + (lane >> 2);
                int c0 = wb + (lane & 3);
                ah[ii][0] = Ah[r * 20 + c0];
                ah[ii][1] = Ah[(r + 8) * 20 + c0];
                ah[ii][2] = Ah[r * 20 + c0 + 4];
                ah[ii][3] = Ah[(r + 8) * 20 + c0 + 4];
                al[ii][0] = Al[r * 20 + c0];
                al[ii][1] = Al[(r + 8) * 20 + c0];
                al[ii][2] = Al[r * 20 + c0 + 4];
                al[ii][3] = Al[(r + 8) * 20 + c0 + 4];
            }
            uint32_t bh[4][2], bl[4][2];
#pragma unroll
            for (int jj = 0; jj < 4; jj++) {
                int n = wj + jj * 8 + (lane >> 2);
                int c0 = wb + (lane & 3);
                bh[jj][0] = Bh[n * 20 + c0];
                bh[jj][1] = Bh[n * 20 + c0 + 4];
                bl[jj][0] = Bl[n * 20 + c0];
                bl[jj][1] = Bl[n * 20 + c0 + 4];
            }
#pragma unroll
            for (int ii = 0; ii < 2; ii++)
#pragma unroll
                for (int jj = 0; jj < 4; jj++) {
                    mma_bf16(acc[ii][jj], ah[ii], bh[jj]);
                    mma_bf16(acc[ii][jj], ah[ii], bl[jj]);
                    mma_bf16(acc[ii][jj], al[ii], bh[jj]);
                }
        }

        if (s + 1 < 32) {
            uint32_t* nb = smw + ((s + 1) & 1) * STGW;
            *(uint4*)(nb + ar * 20 + ahalf * 8)          = aH0;
            *(uint4*)(nb + ar * 20 + ahalf * 8 + 4)      = aH1;
            *(uint4*)(nb + AW + ar * 20 + ahalf * 8)     = aL0;
            *(uint4*)(nb + AW + ar * 20 + ahalf * 8 + 4) = aL1;
            *(uint4*)(nb + 2 * AW + br * 20 + bq * 4)      = bH;
            *(uint4*)(nb + 2 * AW + BW + br * 20 + bq * 4) = bL;
        }
        __syncthreads();
    }

    float* sO = (float*)smw;
#pragma unroll
    for (int ii = 0; ii < 2; ii++)
#pragma unroll
        for (int jj = 0; jj < 4; jj++) {
            int r = wi + ii * 16 + (lane >> 2);
            int o = wj + jj * 8 + (lane & 3) * 2;
            float b0v = __ldg(&bc[o]), b1v = __ldg(&bc[o + 1]);
            sO[o * 140 + r]           = leaky(acc[ii][jj][0] + b0v);
            sO[(o + 1) * 140 + r]     = leaky(acc[ii][jj][1] + b1v);
            sO[o * 140 + r + 8]       = leaky(acc[ii][jj][2] + b0v);
            sO[(o + 1) * 140 + r + 8] = leaky(acc[ii][jj][3] + b1v);
        }
    __syncthreads();

    int oo = tid >> 2, c4 = (tid & 3) * 4;
    float* orow = out + (size_t)b * (OUTC * NN) + (size_t)oo * NN + n0;
#pragma unroll
    for (int q = 0; q < 8; q++) {
        float4 v = *(float4*)&sO[oo * 140 + c4 + q * 16];
        *(float4*)&orow[c4 + q * 16] = v;
    }
}

extern "C" void kernel_launch(void* const* d_in, const int* in_sizes, int n_in,
                              void* d_out, int out_size) {
    const float* xyz  = (const float*)d_in[0];
    const float* feat = (const float*)d_in[1];
    const float* W1 = (const float*)d_in[2];
    const float* b1 = (const float*)d_in[3];
    const float* W2 = (const float*)d_in[4];
    const float* b2 = (const float*)d_in[5];
    const float* W3 = (const float*)d_in[6];
    const float* b3 = (const float*)d_in[7];
    const float* Wc = (const float*)d_in[8];
    const float* bc = (const float*)d_in[9];

    float* out = (float*)d_out;
    float* out_main = out;
    const int xyz_elems = BB * NN * 3;
    const int out_elems = BB * OUTC * NN;
    if (out_size == xyz_elems + out_elems) {
        cudaMemcpyAsync(out, xyz, (size_t)xyz_elems * sizeof(float), cudaMemcpyDeviceToDevice);
        out_main = out + xyz_elems;
    }

    // ncu captures global launch index 3 -> projgen this round
    bin_kernel<<<BB, 1024>>>(xyz);                                             // 0

    cudaFuncSetAttribute(knn_kernel, cudaFuncAttributeMaxDynamicSharedMemorySize, (int)KNN_SMEM);
    knn_kernel<<<dim3(NN / 32, BB), 256, KNN_SMEM>>>();                        // 1

    transpose_kernel<<<dim3(NN / 32, CC / 32, BB), dim3(32, 8)>>>(feat);       // 2

    projgen_kernel<<<(BB * NN) / (PJW * CW), 128>>>(W1, b1, W2, b2, W3, b3);   // 3

    wcperm_kernel<<<(OUTC * 512) / 256, 256>>>(Wc);                            // 4

    cudaFuncSetAttribute(gemm_bf16_kernel, cudaFuncAttributeMaxDynamicSharedMemorySize, GEMM_SMEM_BYTES);
    gemm_bf16_kernel<<<(BB * NN) / 128, 256, GEMM_SMEM_BYTES>>>(bc, out_main); // 5
}

// round 11
// speedup vs baseline: 1.1655x; 1.1655x over previous
#include <cuda_runtime.h>
#include <cuda_bf16.h>
#include <cstdint>

#define BB 8
#define NN 4096
#define CC 64
#define OUTC 64
#define NS 32
#define R2C 0.04f
#define ALPHA 0.2f
#define CAPK 224
#define NCELL 1000
// full float bits of 0.0225f (= 0.15^2), exact tight threshold on the d2 word
#define TIGHT32 0x3CB850EBu
#define TIGHTKEY64 ((unsigned long long)TIGHT32 << 32)

// ---- device scratch (allocation-free rule) ----
__device__ float g_featT[(size_t)BB * NN * CC];                 // (B,N,C) 8 MB
__device__ __nv_bfloat16 g_projLb[(size_t)BB * NN * 2048];      // per row: hi[1024], lo[1024]
__device__ __nv_bfloat16 g_WcPb[(size_t)OUTC * 2048];           // per row: hi[1024], lo[1024]
__device__ int   g_idx[(size_t)BB * NN * NS];
__device__ float g_gx [(size_t)BB * NN * NS];
__device__ float g_gy [(size_t)BB * NN * NS];
__device__ float g_gz [(size_t)BB * NN * NS];
__device__ float4 g_pts4[(size_t)BB * NN];                      // cell-sorted {x,y,z,origIdx}
__device__ int   g_cellStart[(size_t)BB * (NCELL + 1)];

__device__ __forceinline__ float leaky(float x) { return fmaxf(x, ALPHA * x); }

__device__ __forceinline__ uint32_t pack_hi(float v0, float v1, float& r0, float& r1) {
    __nv_bfloat16 h0 = __float2bfloat16_rn(v0);
    __nv_bfloat16 h1 = __float2bfloat16_rn(v1);
    r0 = v0 - __bfloat162float(h0);
    r1 = v1 - __bfloat162float(h1);
    uint16_t u0 = *(uint16_t*)&h0, u1 = *(uint16_t*)&h1;
    return ((uint32_t)u1 << 16) | u0;
}
__device__ __forceinline__ uint32_t pack_bf2(float v0, float v1) {
    __nv_bfloat16 h0 = __float2bfloat16_rn(v0);
    __nv_bfloat16 h1 = __float2bfloat16_rn(v1);
    uint16_t u0 = *(uint16_t*)&h0, u1 = *(uint16_t*)&h1;
    return ((uint32_t)u1 << 16) | u0;
}

__device__ __forceinline__ void mma_bf16(float* c, const uint32_t* a, const uint32_t* b) {
    asm volatile(
        "mma.sync.aligned.m16n8k16.row.col.f32.bf16.bf16.f32 "
        "{%0,%1,%2,%3}, {%4,%5,%6,%7}, {%8,%9}, {%0,%1,%2,%3};"
        : "+f"(c[0]), "+f"(c[1]), "+f"(c[2]), "+f"(c[3])
        : "r"(a[0]), "r"(a[1]), "r"(a[2]), "r"(a[3]), "r"(b[0]), "r"(b[1]));
}

// ---------------- transpose: (B,C,N) -> (B,N,C) ----------------
__global__ void transpose_kernel(const float* __restrict__ feat) {
    __shared__ float tile[32][33];
    int b = blockIdx.z, n0 = blockIdx.x * 32, c0 = blockIdx.y * 32;
    int tx = threadIdx.x, ty = threadIdx.y;
    const float* fb = feat + (size_t)b * CC * NN;
    float* ob = g_featT + (size_t)b * NN * CC;
#pragma unroll
    for (int i = 0; i < 4; i++)
        tile[ty + i * 8][tx] = fb[(size_t)(c0 + ty + i * 8) * NN + n0 + tx];
    __syncthreads();
#pragma unroll
    for (int i = 0; i < 4; i++)
        ob[(size_t)(n0 + ty + i * 8) * CC + c0 + tx] = tile[tx][ty + i * 8];
}

// ---------------- Wc permute + bf16 split ----------------
__global__ void wcperm_kernel(const float* __restrict__ Wc) {
    int idx = blockIdx.x * 256 + threadIdx.x;   // 32768 pairs
    int o = idx >> 9, pair = idx & 511;
    int kc0 = pair * 2;
    int c = kc0 & 63, k = kc0 >> 6;
    float x0 = Wc[o * 1024 + c * 16 + k];
    float x1 = Wc[o * 1024 + (c + 1) * 16 + k];
    float r0, r1;
    uint32_t hw = pack_hi(x0, x1, r0, r1);
    uint32_t lw = pack_bf2(r0, r1);
    uint32_t* row = (uint32_t*)(g_WcPb + (size_t)o * 2048);
    row[pair] = hw;
    row[512 + pair] = lw;
}

// ---------------- bin: counting sort into 10^3 cells ----------------
__global__ __launch_bounds__(1024) void bin_kernel(const float* __restrict__ xyz) {
    __shared__ int cnt[NCELL];
    __shared__ int off[NCELL];
    __shared__ int wsum[32];
    int b = blockIdx.x, tid = threadIdx.x, lane = tid & 31, wid = tid >> 5;
    for (int i = tid; i < NCELL; i += 1024) cnt[i] = 0;
    __syncthreads();

    float xs[4], ys[4], zs[4];
    int cell[4];
    const float* xb = xyz + (size_t)b * NN * 3;
#pragma unroll
    for (int t = 0; t < 4; t++) {
        int n = tid * 4 + t;
        xs[t] = xb[n * 3 + 0];
        ys[t] = xb[n * 3 + 1];
        zs[t] = xb[n * 3 + 2];
        int ci = min((int)(xs[t] * 10.f), 9);
        int cj = min((int)(ys[t] * 10.f), 9);
        int ck = min((int)(zs[t] * 10.f), 9);
        cell[t] = (ck * 10 + cj) * 10 + ci;
        atomicAdd(&cnt[cell[t]], 1);
    }
    __syncthreads();

    int v = (tid < NCELL) ? cnt[tid] : 0;
    int orig = v;
#pragma unroll
    for (int d = 1; d < 32; d <<= 1) {
        int t2 = __shfl_up_sync(0xffffffffu, v, d);
        if (lane >= d) v += t2;
    }
    if (lane == 31) wsum[wid] = v;
    __syncthreads();
    if (wid == 0) {
        int s = wsum[lane];
#pragma unroll
        for (int d = 1; d < 32; d <<= 1) {
            int t2 = __shfl_up_sync(0xffffffffu, s, d);
            if (lane >= d) s += t2;
        }
        wsum[lane] = s;
    }
    __syncthreads();
    int excl = v + (wid > 0 ? wsum[wid - 1] : 0) - orig;
    if (tid < NCELL) {
        off[tid] = excl;
        g_cellStart[(size_t)b * (NCELL + 1) + tid] = excl;
    }
    if (tid == 0) g_cellStart[(size_t)b * (NCELL + 1) + NCELL] = NN;
    __syncthreads();

#pragma unroll
    for (int t = 0; t < 4; t++) {
        int n = tid * 4 + t;
        int pos = atomicAdd(&off[cell[t]], 1);
        g_pts4[(size_t)b * NN + pos] = make_float4(xs[t], ys[t], zs[t], __int_as_float(n));
    }
}

// ---------------- KNN: sorted-center shared scan (ballot compaction) + rank selection ----------------
#define KNN_SMEM (size_t)(8 * 4 * CAPK * 8 + (NCELL + 8) * 4)

#define RANK_LOOP(cd, Mlen, kk, rr)                                         \
    do {                                                                    \
        if ((Mlen) <= 64) {                                                 \
            for (int q = 0; q < (Mlen); q++) {                              \
                unsigned long long kq = (cd)[q];                            \
                rr[0] += (kq < kk[0]); rr[1] += (kq < kk[1]);               \
            }                                                               \
        } else if ((Mlen) <= 128) {                                         \
            for (int q = 0; q < (Mlen); q++) {                              \
                unsigned long long kq = (cd)[q];                            \
                rr[0] += (kq < kk[0]); rr[1] += (kq < kk[1]);               \
                rr[2] += (kq < kk[2]); rr[3] += (kq < kk[3]);               \
            }                                                               \
        } else {                                                            \
            for (int q = 0; q < (Mlen); q++) {                              \
                unsigned long long kq = (cd)[q];                            \
                rr[0] += (kq < kk[0]); rr[1] += (kq < kk[1]);               \
                rr[2] += (kq < kk[2]); rr[3] += (kq < kk[3]);               \
                rr[4] += (kq < kk[4]); rr[5] += (kq < kk[5]);               \
                rr[6] += (kq < kk[6]);                                      \
            }                                                               \
        }                                                                   \
    } while (0)

__global__ __launch_bounds__(256, 3) void knn_kernel() {
    extern __shared__ char smem_raw[];
    unsigned long long* candAll = (unsigned long long*)smem_raw;
    int* scell = (int*)(candAll + 8 * 4 * CAPK);

    int b = blockIdx.y, tid = threadIdx.x, w = tid >> 5, lane = tid & 31;
    const int* cs = g_cellStart + (size_t)b * (NCELL + 1);
    for (int i = tid; i < NCELL + 1; i += 256) scell[i] = cs[i];
    __syncthreads();

    int nbase = blockIdx.x * 32 + w * 4;       // sorted position base
    unsigned long long* cand0 = candAll + (size_t)w * 4 * CAPK;
    const float4* pts = g_pts4 + (size_t)b * NN;
    unsigned lmask = (1u << lane) - 1u;

    float cx[4], cy[4], cz[4];
    int oidx[4], cnt[4];
#pragma unroll
    for (int i = 0; i < 4; i++) {
        float4 c = pts[nbase + i];
        cx[i] = c.x; cy[i] = c.y; cz[i] = c.z;
        oidx[i] = __float_as_int(c.w);
        cnt[i] = 0;
    }

    // union window over the 4 co-located centers
    int xlo = 9, xhi = 0, ylo = 9, yhi = 0, zlo = 9, zhi = 0;
#pragma unroll
    for (int i = 0; i < 4; i++) {
        int cxi = min((int)(cx[i] * 10.f), 9);
        int cyi = min((int)(cy[i] * 10.f), 9);
        int czi = min((int)(cz[i] * 10.f), 9);
        xlo = min(xlo, max(cxi - 2, 0)); xhi = max(xhi, min(cxi + 2, 9));
        ylo = min(ylo, max(cyi - 2, 0)); yhi = max(yhi, min(cyi + 2, 9));
        zlo = min(zlo, max(czi - 2, 0)); zhi = max(zhi, min(czi + 2, 9));
    }

    // shared scan with ballot compaction (all lanes reach the ballot)
    for (int zz = zlo; zz <= zhi; zz++) {
        for (int yy = ylo; yy <= yhi; yy++) {
            int rb = (zz * 10 + yy) * 10;
            int s = scell[rb + xlo], e = scell[rb + xhi + 1];
            for (int base = s; base < e; base += 32) {
                int p = base + lane;
                bool valid = (p < e);
                float4 pt = pts[valid ? p : s];   // clamped dummy read (in-bounds)
                unsigned lowbase = ((unsigned)__float_as_int(pt.w) << 12) | (unsigned)p;
#pragma unroll
                for (int i = 0; i < 4; i++) {
                    float dx = pt.x - cx[i], dy = pt.y - cy[i], dz = pt.z - cz[i];
                    float d2 = fmaf(dx, dx, fmaf(dy, dy, dz * dz));
                    bool in = valid && (d2 <= R2C);
                    unsigned m = __ballot_sync(0xffffffffu, in);
                    if (in) {
                        int pos = cnt[i] + __popc(m & lmask);
                        if (pos < CAPK)
                            cand0[i * CAPK + pos] =
                                ((unsigned long long)__float_as_uint(d2) << 32) | lowbase;
                    }
                    cnt[i] += __popc(m);
                }
            }
        }
    }
    __syncwarp();

#pragma unroll
    for (int i = 0; i < 4; i++) {
        size_t cg = (size_t)b * NN + oidx[i];
        int M = min(cnt[i], CAPK);
        unsigned long long* cd = cand0 + i * CAPK;

        if (lane >= M) {
            g_idx[cg * NS + lane] = oidx[i];
            g_gx[cg * NS + lane] = 0.0f;
            g_gy[cg * NS + lane] = 0.0f;
            g_gz[cg * NS + lane] = 0.0f;
        }

        unsigned long long k[7];
#pragma unroll
        for (int t = 0; t < 7; t++) {
            int p = lane + 32 * t;
            k[t] = (p < M) ? cd[p] : ~0ull;
        }
        unsigned bms[7];
        int Mt = 0;
#pragma unroll
        for (int t = 0; t < 7; t++) {
            bms[t] = __ballot_sync(0xffffffffu, k[t] < TIGHTKEY64);
            Mt += __popc(bms[t]);
        }

        if (Mt >= NS) {
            int base = 0;
#pragma unroll
            for (int t = 0; t < 7; t++) {
                if (k[t] < TIGHTKEY64)
                    cd[base + __popc(bms[t] & lmask)] = k[t];
                base += __popc(bms[t]);
            }
            __syncwarp();
            unsigned long long k2[7];
            int rr[7];
#pragma unroll
            for (int t = 0; t < 7; t++) {
                int p = lane + 32 * t;
                k2[t] = (p < Mt) ? cd[p] : ~0ull;
                rr[t] = 0;
            }
            RANK_LOOP(cd, Mt, k2, rr);
#pragma unroll
            for (int t = 0; t < 7; t++) {
                int p = lane + 32 * t;
                if (p < Mt && rr[t] < NS) {
                    int low = (int)(k2[t] & 0xffffffffull);
                    int jj = (low >> 12) & 0xFFF;
                    float4 p4 = pts[low & 0xFFF];
                    g_idx[cg * NS + rr[t]] = jj;
                    g_gx[cg * NS + rr[t]] = p4.x - cx[i];
                    g_gy[cg * NS + rr[t]] = p4.y - cy[i];
                    g_gz[cg * NS + rr[t]] = p4.z - cz[i];
                }
            }
        } else {
            int rr[7];
#pragma unroll
            for (int t = 0; t < 7; t++) rr[t] = 0;
            RANK_LOOP(cd, M, k, rr);
#pragma unroll
            for (int t = 0; t < 7; t++) {
                int p = lane + 32 * t;
                if (p < M && rr[t] < NS) {
                    int low = (int)(k[t] & 0xffffffffull);
                    int jj = (low >> 12) & 0xFFF;
                    float4 p4 = pts[low & 0xFFF];
                    g_idx[cg * NS + rr[t]] = jj;
                    g_gx[cg * NS + rr[t]] = p4.x - cx[i];
                    g_gy[cg * NS + rr[t]] = p4.y - cy[i];
                    g_gz[cg * NS + rr[t]] = p4.z - cz[i];
                }
            }
        }
        __syncwarp();
    }
}

// ---------------- projgen: MLP + normalize + rank-32 proj, bf16-split output (R9 scalar) ----------------
#define CW 2
__global__ __launch_bounds__(256) void projgen_kernel(
    const float* __restrict__ W1, const float* __restrict__ b1,
    const float* __restrict__ W2, const float* __restrict__ b2,
    const float* __restrict__ W3, const float* __restrict__ b3)
{
    __shared__ float swfAll[8][512];
    __shared__ int   snjAll[8][32];
    __shared__ float sW[448];

    int tid = threadIdx.x, w = tid >> 5, lane = tid & 31;
    if (tid < 24)  sW[tid] = W1[tid];
    if (tid < 8)   sW[24 + tid] = b1[tid];
    if (tid < 128) sW[32 + tid] = W2[tid];
    if (tid < 16)  sW[160 + tid] = b2[tid];
    sW[176 + tid] = W3[tid];
    if (tid < 16)  sW[432 + tid] = b3[tid];
    __syncthreads();

    float* swf = swfAll[w];
    int* snj = snjAll[w];

    for (int it = 0; it < CW; it++) {
        size_t cg = (size_t)blockIdx.x * (8 * CW) + w * CW + it;
        int bb = (int)(cg >> 12);

        int   nj = g_idx[cg * NS + lane];
        float gx = g_gx[cg * NS + lane];
        float gy = g_gy[cg * NS + lane];
        float gz = g_gz[cg * NS + lane];

        float h1[8];
#pragma unroll
        for (int o = 0; o < 8; o++)
            h1[o] = leaky(fmaf(sW[o*3+0], gx, fmaf(sW[o*3+1], gy, fmaf(sW[o*3+2], gz, sW[24+o]))));
        float h2[16];
#pragma unroll
        for (int o = 0; o < 16; o++) {
            float a = sW[160 + o];
#pragma unroll
            for (int i = 0; i < 8; i++) a = fmaf(sW[32 + o*8 + i], h1[i], a);
            h2[o] = leaky(a);
        }
        float wv[16], w2sum = 0.0f;
#pragma unroll
        for (int o = 0; o < 16; o++) {
            float a = sW[432 + o];
#pragma unroll
            for (int i = 0; i < 16; i++) a = fmaf(sW[176 + o*16 + i], h2[i], a);
            wv[o] = a; w2sum = fmaf(a, a, w2sum);
        }
        float inv1 = rsqrtf(fmaxf(w2sum, 1e-8f));

        float wn[16];
#pragma unroll
        for (int kk = 0; kk < 16; kk++) {
            float t = wv[kk] * wv[kk];
#pragma unroll
            for (int off = 16; off; off >>= 1) t += __shfl_xor_sync(0xffffffffu, t, off);
            float s2 = fmaxf(sqrtf(fmaxf(t, 1e-8f)), 1.0f);
            wn[kk] = wv[kk] * inv1 * (1.0f / s2);
        }

        float4* swf4 = (float4*)swf;
#pragma unroll
        for (int q = 0; q < 4; q++)
            swf4[q * 32 + lane] = make_float4(wn[4*q], wn[4*q+1], wn[4*q+2], wn[4*q+3]);
        snj[lane] = nj;
        __syncwarp();

        const float* fT = g_featT + (size_t)bb * NN * CC;
        float2 buf[8];
#pragma unroll
        for (int p = 0; p < 8; p++)
            buf[p] = *(const float2*)(fT + (size_t)snj[p] * CC + 2 * lane);

        float acc0[16], acc1[16];
#pragma unroll
        for (int kk = 0; kk < 16; kk++) { acc0[kk] = 0.0f; acc1[kk] = 0.0f; }

#pragma unroll
        for (int s = 0; s < 32; s++) {
            float2 f = buf[s & 7];
            if (s < 24)
                buf[s & 7] = *(const float2*)(fT + (size_t)snj[s + 8] * CC + 2 * lane);
            float4 q0 = swf4[s], q1 = swf4[32 + s], q2 = swf4[64 + s], q3 = swf4[96 + s];
            acc0[0]  = fmaf(q0.x, f.x, acc0[0]);  acc1[0]  = fmaf(q0.x, f.y, acc1[0]);
            acc0[1]  = fmaf(q0.y, f.x, acc0[1]);  acc1[1]  = fmaf(q0.y, f.y, acc1[1]);
            acc0[2]  = fmaf(q0.z, f.x, acc0[2]);  acc1[2]  = fmaf(q0.z, f.y, acc1[2]);
            acc0[3]  = fmaf(q0.w, f.x, acc0[3]);  acc1[3]  = fmaf(q0.w, f.y, acc1[3]);
            acc0[4]  = fmaf(q1.x, f.x, acc0[4]);  acc1[4]  = fmaf(q1.x, f.y, acc1[4]);
            acc0[5]  = fmaf(q1.y, f.x, acc0[5]);  acc1[5]  = fmaf(q1.y, f.y, acc1[5]);
            acc0[6]  = fmaf(q1.z, f.x, acc0[6]);  acc1[6]  = fmaf(q1.z, f.y, acc1[6]);
            acc0[7]  = fmaf(q1.w, f.x, acc0[7]);  acc1[7]  = fmaf(q1.w, f.y, acc1[7]);
            acc0[8]  = fmaf(q2.x, f.x, acc0[8]);  acc1[8]  = fmaf(q2.x, f.y, acc1[8]);
            acc0[9]  = fmaf(q2.y, f.x, acc0[9]);  acc1[9]  = fmaf(q2.y, f.y, acc1[9]);
            acc0[10] = fmaf(q2.z, f.x, acc0[10]); acc1[10] = fmaf(q2.z, f.y, acc1[10]);
            acc0[11] = fmaf(q2.w, f.x, acc0[11]); acc1[11] = fmaf(q2.w, f.y, acc1[11]);
            acc0[12] = fmaf(q3.x, f.x, acc0[12]); acc1[12] = fmaf(q3.x, f.y, acc1[12]);
            acc0[13] = fmaf(q3.y, f.x, acc0[13]); acc1[13] = fmaf(q3.y, f.y, acc1[13]);
            acc0[14] = fmaf(q3.z, f.x, acc0[14]); acc1[14] = fmaf(q3.z, f.y, acc1[14]);
            acc0[15] = fmaf(q3.w, f.x, acc0[15]); acc1[15] = fmaf(q3.w, f.y, acc1[15]);
        }

        uint32_t* row = (uint32_t*)(g_projLb + cg * 2048);
#pragma unroll
        for (int kk = 0; kk < 16; kk++) {
            float v0 = leaky(acc0[kk]), v1 = leaky(acc1[kk]);
            float r0, r1;
            uint32_t hw = pack_hi(v0, v1, r0, r1);
            uint32_t lw = pack_bf2(r0, r1);
            row[kk * 32 + lane] = hw;
            row[512 + kk * 32 + lane] = lw;
        }
        __syncwarp();
    }
}

// ---------------- GEMM (bf16 hi/lo split, m16n8k16) ----------------
#define AW (128 * 20)
#define BW (64 * 20)
#define STGW (2 * AW + 2 * BW)
#define GEMM_SMEM_BYTES (2 * STGW * 4)

__global__ __launch_bounds__(256) void gemm_bf16_kernel(
    const float* __restrict__ bc, float* __restrict__ out)
{
    extern __shared__ uint32_t smw[];
    int tid = threadIdx.x, lane = tid & 31, w = tid >> 5;
    size_t row0 = (size_t)blockIdx.x * 128;
    int b = (int)(row0 >> 12), n0 = (int)(row0 & 4095);

    int ar = tid >> 1, ahalf = tid & 1;
    int br = tid >> 2, bq = tid & 3;

    const uint32_t* rowA = (const uint32_t*)(g_projLb + (row0 + ar) * 2048);
    const uint32_t* rowB = (const uint32_t*)(g_WcPb + (size_t)br * 2048);

    int wi = (w & 3) * 32;
    int wj = (w >> 2) * 32;

    float acc[2][4][4];
#pragma unroll
    for (int i = 0; i < 2; i++)
#pragma unroll
        for (int j = 0; j < 4; j++)
#pragma unroll
            for (int q = 0; q < 4; q++) acc[i][j][q] = 0.0f;

    uint4 aH0, aH1, aL0, aL1, bH, bL;
    {
        const uint4* pAh = (const uint4*)(rowA + ahalf * 8);
        const uint4* pAl = (const uint4*)(rowA + 512 + ahalf * 8);
        aH0 = pAh[0]; aH1 = pAh[1]; aL0 = pAl[0]; aL1 = pAl[1];
        bH = *(const uint4*)(rowB + bq * 4);
        bL = *(const uint4*)(rowB + 512 + bq * 4);
    }
    {
        uint32_t* buf = smw;
        *(uint4*)(buf + ar * 20 + ahalf * 8)          = aH0;
        *(uint4*)(buf + ar * 20 + ahalf * 8 + 4)      = aH1;
        *(uint4*)(buf + AW + ar * 20 + ahalf * 8)     = aL0;
        *(uint4*)(buf + AW + ar * 20 + ahalf * 8 + 4) = aL1;
        *(uint4*)(buf + 2 * AW + br * 20 + bq * 4)          = bH;
        *(uint4*)(buf + 2 * AW + BW + br * 20 + bq * 4)     = bL;
    }
    __syncthreads();

    for (int s = 0; s < 32; s++) {
        if (s + 1 < 32) {
            int wb = (s + 1) * 16;
            const uint4* pAh = (const uint4*)(rowA + wb + ahalf * 8);
            const uint4* pAl = (const uint4*)(rowA + 512 + wb + ahalf * 8);
            aH0 = pAh[0]; aH1 = pAh[1]; aL0 = pAl[0]; aL1 = pAl[1];
            bH = *(const uint4*)(rowB + wb + bq * 4);
            bL = *(const uint4*)(rowB + 512 + wb + bq * 4);
        }
        const uint32_t* buf = smw + (s & 1) * STGW;
        const uint32_t* Ah = buf;
        const uint32_t* Al = buf + AW;
        const uint32_t* Bh = buf + 2 * AW;
        const uint32_t* Bl = buf + 2 * AW + BW;

#pragma unroll
        for (int t = 0; t < 2; t++) {
            int wb = t * 8;
            uint32_t ah[2][4], al[2][4];
#pragma unroll
            for (int ii = 0; ii < 2; ii++) {
                int r = wi + ii * 16 + (lane >> 2);
                int c0 = wb + (lane & 3);
                ah[ii][0] = Ah[r * 20 + c0];
                ah[ii][1] = Ah[(r + 8) * 20 + c0];
                ah[ii][2] = Ah[r * 20 + c0 + 4];
                ah[ii][3] = Ah[(r + 8) * 20 + c0 + 4];
                al[ii][0] = Al[r * 20 + c0];
                al[ii][1] = Al[(r + 8) * 20 + c0];
                al[ii][2] = Al[r * 20 + c0 + 4];
                al[ii][3] = Al[(r + 8) * 20 + c0 + 4];
            }
            uint32_t bh[4][2], bl[4][2];
#pragma unroll
            for (int jj = 0; jj < 4; jj++) {
                int n = wj + jj * 8 + (lane >> 2);
                int c0 = wb + (lane & 3);
                bh[jj][0] = Bh[n * 20 + c0];
                bh[jj][1] = Bh[n * 20 + c0 + 4];
                bl[jj][0] = Bl[n * 20 + c0];
                bl[jj][1] = Bl[n * 20 + c0 + 4];
            }
#pragma unroll
            for (int ii = 0; ii < 2; ii++)
#pragma unroll
                for (int jj = 0; jj < 4; jj++) {
                    mma_bf16(acc[ii][jj], ah[ii], bh[jj]);
                    mma_bf16(acc[ii][jj], ah[ii], bl[jj]);
                    mma_bf16(acc[ii][jj], al[ii], bh[jj]);
                }
        }

        if (s + 1 < 32) {
            uint32_t* nb = smw + ((s + 1) & 1) * STGW;
            *(uint4*)(nb + ar * 20 + ahalf * 8)          = aH0;
            *(uint4*)(nb + ar * 20 + ahalf * 8 + 4)      = aH1;
            *(uint4*)(nb + AW + ar * 20 + ahalf * 8)     = aL0;
            *(uint4*)(nb + AW + ar * 20 + ahalf * 8 + 4) = aL1;
            *(uint4*)(nb + 2 * AW + br * 20 + bq * 4)      = bH;
            *(uint4*)(nb + 2 * AW + BW + br * 20 + bq * 4) = bL;
        }
        __syncthreads();
    }

    float* sO = (float*)smw;
#pragma unroll
    for (int ii = 0; ii < 2; ii++)
#pragma unroll
        for (int jj = 0; jj < 4; jj++) {
            int r = wi + ii * 16 + (lane >> 2);
            int o = wj + jj * 8 + (lane & 3) * 2;
            float b0v = __ldg(&bc[o]), b1v = __ldg(&bc[o + 1]);
            sO[o * 140 + r]           = leaky(acc[ii][jj][0] + b0v);
            sO[(o + 1) * 140 + r]     = leaky(acc[ii][jj][1] + b1v);
            sO[o * 140 + r + 8]       = leaky(acc[ii][jj][2] + b0v);
            sO[(o + 1) * 140 + r + 8] = leaky(acc[ii][jj][3] + b1v);
        }
    __syncthreads();

    int oo = tid >> 2, c4 = (tid & 3) * 4;
    float* orow = out + (size_t)b * (OUTC * NN) + (size_t)oo * NN + n0;
#pragma unroll
    for (int q = 0; q < 8; q++) {
        float4 v = *(float4*)&sO[oo * 140 + c4 + q * 16];
        *(float4*)&orow[c4 + q * 16] = v;
    }
}

extern "C" void kernel_launch(void* const* d_in, const int* in_sizes, int n_in,
                              void* d_out, int out_size) {
    const float* xyz  = (const float*)d_in[0];
    const float* feat = (const float*)d_in[1];
    const float* W1 = (const float*)d_in[2];
    const float* b1 = (const float*)d_in[3];
    const float* W2 = (const float*)d_in[4];
    const float* b2 = (const float*)d_in[5];
    const float* W3 = (const float*)d_in[6];
    const float* b3 = (const float*)d_in[7];
    const float* Wc = (const float*)d_in[8];
    const float* bc = (const float*)d_in[9];

    float* out = (float*)d_out;
    float* out_main = out;
    const int xyz_elems = BB * NN * 3;
    const int out_elems = BB * OUTC * NN;
    if (out_size == xyz_elems + out_elems) {
        cudaMemcpyAsync(out, xyz, (size_t)xyz_elems * sizeof(float), cudaMemcpyDeviceToDevice);
        out_main = out + xyz_elems;
    }

    // ncu captures global launch index 3 -> knn_kernel
    transpose_kernel<<<dim3(NN / 32, CC / 32, BB), dim3(32, 8)>>>(feat);      // 0
    wcperm_kernel<<<(OUTC * 512) / 256, 256>>>(Wc);                            // 1
    bin_kernel<<<BB, 1024>>>(xyz);                                             // 2

    cudaFuncSetAttribute(knn_kernel, cudaFuncAttributeMaxDynamicSharedMemorySize, (int)KNN_SMEM);
    knn_kernel<<<dim3(NN / 32, BB), 256, KNN_SMEM>>>();                        // 3

    projgen_kernel<<<(BB * NN) / (8 * CW), 256>>>(W1, b1, W2, b2, W3, b3);     // 4

    cudaFuncSetAttribute(gemm_bf16_kernel, cudaFuncAttributeMaxDynamicSharedMemorySize, GEMM_SMEM_BYTES);
    gemm_bf16_kernel<<<(BB * NN) / 128, 256, GEMM_SMEM_BYTES>>>(bc, out_main); // 5
}

// round 12
// speedup vs baseline: 1.1935x; 1.0240x over previous
#include <cuda_runtime.h>
#include <cuda_bf16.h>
#include <cstdint>

#define BB 8
#define NN 4096
#define CC 64
#define OUTC 64
#define NS 32
#define R2C 0.04f
#define ALPHA 0.2f
#define CAPK 224
#define NCELL 1000
// full float bits of 0.0225f (= 0.15^2), exact tight threshold on the d2 word
#define TIGHT32 0x3CB850EBu
#define TIGHTKEY64 ((unsigned long long)TIGHT32 << 32)

// ---- device scratch (allocation-free rule) ----
__device__ float g_featT[(size_t)BB * NN * CC];                 // (B,N,C) 8 MB
__device__ __nv_bfloat16 g_projLb[(size_t)BB * NN * 2048];      // per row: hi[1024], lo[1024]
__device__ __nv_bfloat16 g_WcPb[(size_t)OUTC * 2048];           // per row: hi[1024], lo[1024]
__device__ int   g_idx[(size_t)BB * NN * NS];
__device__ float g_gx [(size_t)BB * NN * NS];
__device__ float g_gy [(size_t)BB * NN * NS];
__device__ float g_gz [(size_t)BB * NN * NS];
__device__ float4 g_pts4[(size_t)BB * NN];                      // cell-sorted {x,y,z,origIdx}
__device__ int   g_cellStart[(size_t)BB * (NCELL + 1)];

__device__ __forceinline__ float leaky(float x) { return fmaxf(x, ALPHA * x); }

__device__ __forceinline__ uint32_t pack_hi(float v0, float v1, float& r0, float& r1) {
    __nv_bfloat16 h0 = __float2bfloat16_rn(v0);
    __nv_bfloat16 h1 = __float2bfloat16_rn(v1);
    r0 = v0 - __bfloat162float(h0);
    r1 = v1 - __bfloat162float(h1);
    uint16_t u0 = *(uint16_t*)&h0, u1 = *(uint16_t*)&h1;
    return ((uint32_t)u1 << 16) | u0;
}
__device__ __forceinline__ uint32_t pack_bf2(float v0, float v1) {
    __nv_bfloat16 h0 = __float2bfloat16_rn(v0);
    __nv_bfloat16 h1 = __float2bfloat16_rn(v1);
    uint16_t u0 = *(uint16_t*)&h0, u1 = *(uint16_t*)&h1;
    return ((uint32_t)u1 << 16) | u0;
}

__device__ __forceinline__ void mma_bf16(float* c, const uint32_t* a, const uint32_t* b) {
    asm volatile(
        "mma.sync.aligned.m16n8k16.row.col.f32.bf16.bf16.f32 "
        "{%0,%1,%2,%3}, {%4,%5,%6,%7}, {%8,%9}, {%0,%1,%2,%3};"
        : "+f"(c[0]), "+f"(c[1]), "+f"(c[2]), "+f"(c[3])
        : "r"(a[0]), "r"(a[1]), "r"(a[2]), "r"(a[3]), "r"(b[0]), "r"(b[1]));
}

// ---------------- transpose: (B,C,N) -> (B,N,C) ----------------
__global__ void transpose_kernel(const float* __restrict__ feat) {
    __shared__ float tile[32][33];
    int b = blockIdx.z, n0 = blockIdx.x * 32, c0 = blockIdx.y * 32;
    int tx = threadIdx.x, ty = threadIdx.y;
    const float* fb = feat + (size_t)b * CC * NN;
    float* ob = g_featT + (size_t)b * NN * CC;
#pragma unroll
    for (int i = 0; i < 4; i++)
        tile[ty + i * 8][tx] = fb[(size_t)(c0 + ty + i * 8) * NN + n0 + tx];
    __syncthreads();
#pragma unroll
    for (int i = 0; i < 4; i++)
        ob[(size_t)(n0 + ty + i * 8) * CC + c0 + tx] = tile[tx][ty + i * 8];
}

// ---------------- Wc permute + bf16 split ----------------
__global__ void wcperm_kernel(const float* __restrict__ Wc) {
    int idx = blockIdx.x * 256 + threadIdx.x;   // 32768 pairs
    int o = idx >> 9, pair = idx & 511;
    int kc0 = pair * 2;
    int c = kc0 & 63, k = kc0 >> 6;
    float x0 = Wc[o * 1024 + c * 16 + k];
    float x1 = Wc[o * 1024 + (c + 1) * 16 + k];
    float r0, r1;
    uint32_t hw = pack_hi(x0, x1, r0, r1);
    uint32_t lw = pack_bf2(r0, r1);
    uint32_t* row = (uint32_t*)(g_WcPb + (size_t)o * 2048);
    row[pair] = hw;
    row[512 + pair] = lw;
}

// ---------------- bin: counting sort into 10^3 cells ----------------
__global__ __launch_bounds__(1024) void bin_kernel(const float* __restrict__ xyz) {
    __shared__ int cnt[NCELL];
    __shared__ int off[NCELL];
    __shared__ int wsum[32];
    int b = blockIdx.x, tid = threadIdx.x, lane = tid & 31, wid = tid >> 5;
    for (int i = tid; i < NCELL; i += 1024) cnt[i] = 0;
    __syncthreads();

    float xs[4], ys[4], zs[4];
    int cell[4];
    const float* xb = xyz + (size_t)b * NN * 3;
#pragma unroll
    for (int t = 0; t < 4; t++) {
        int n = tid * 4 + t;
        xs[t] = xb[n * 3 + 0];
        ys[t] = xb[n * 3 + 1];
        zs[t] = xb[n * 3 + 2];
        int ci = min((int)(xs[t] * 10.f), 9);
        int cj = min((int)(ys[t] * 10.f), 9);
        int ck = min((int)(zs[t] * 10.f), 9);
        cell[t] = (ck * 10 + cj) * 10 + ci;
        atomicAdd(&cnt[cell[t]], 1);
    }
    __syncthreads();

    int v = (tid < NCELL) ? cnt[tid] : 0;
    int orig = v;
#pragma unroll
    for (int d = 1; d < 32; d <<= 1) {
        int t2 = __shfl_up_sync(0xffffffffu, v, d);
        if (lane >= d) v += t2;
    }
    if (lane == 31) wsum[wid] = v;
    __syncthreads();
    if (wid == 0) {
        int s = wsum[lane];
#pragma unroll
        for (int d = 1; d < 32; d <<= 1) {
            int t2 = __shfl_up_sync(0xffffffffu, s, d);
            if (lane >= d) s += t2;
        }
        wsum[lane] = s;
    }
    __syncthreads();
    int excl = v + (wid > 0 ? wsum[wid - 1] : 0) - orig;
    if (tid < NCELL) {
        off[tid] = excl;
        g_cellStart[(size_t)b * (NCELL + 1) + tid] = excl;
    }
    if (tid == 0) g_cellStart[(size_t)b * (NCELL + 1) + NCELL] = NN;
    __syncthreads();

#pragma unroll
    for (int t = 0; t < 4; t++) {
        int n = tid * 4 + t;
        int pos = atomicAdd(&off[cell[t]], 1);
        g_pts4[(size_t)b * NN + pos] = make_float4(xs[t], ys[t], zs[t], __int_as_float(n));
    }
}

// ---------------- KNN: sorted-center shared scan (R9 atomic form) + rank selection ----------------
#define KNN_SMEM (size_t)(8 * 4 * CAPK * 8 + (NCELL + 8) * 4 + 32 * 4)

#define RANK_LOOP(cd, Mlen, kk, rr)                                         \
    do {                                                                    \
        if ((Mlen) <= 64) {                                                 \
            for (int q = 0; q < (Mlen); q++) {                              \
                unsigned long long kq = (cd)[q];                            \
                rr[0] += (kq < kk[0]); rr[1] += (kq < kk[1]);               \
            }                                                               \
        } else if ((Mlen) <= 128) {                                         \
            for (int q = 0; q < (Mlen); q++) {                              \
                unsigned long long kq = (cd)[q];                            \
                rr[0] += (kq < kk[0]); rr[1] += (kq < kk[1]);               \
                rr[2] += (kq < kk[2]); rr[3] += (kq < kk[3]);               \
            }                                                               \
        } else {                                                            \
            for (int q = 0; q < (Mlen); q++) {                              \
                unsigned long long kq = (cd)[q];                            \
                rr[0] += (kq < kk[0]); rr[1] += (kq < kk[1]);               \
                rr[2] += (kq < kk[2]); rr[3] += (kq < kk[3]);               \
                rr[4] += (kq < kk[4]); rr[5] += (kq < kk[5]);               \
                rr[6] += (kq < kk[6]);                                      \
            }                                                               \
        }                                                                   \
    } while (0)

__global__ __launch_bounds__(256, 3) void knn_kernel() {
    extern __shared__ char smem_raw[];
    unsigned long long* candAll = (unsigned long long*)smem_raw;
    int* scell = (int*)(candAll + 8 * 4 * CAPK);
    int* scnt = scell + (NCELL + 8);

    int b = blockIdx.y, tid = threadIdx.x, w = tid >> 5, lane = tid & 31;
    const int* cs = g_cellStart + (size_t)b * (NCELL + 1);
    for (int i = tid; i < NCELL + 1; i += 256) scell[i] = cs[i];
    if (tid < 32) scnt[tid] = 0;
    __syncthreads();

    int nbase = blockIdx.x * 32 + w * 4;       // sorted position base
    unsigned long long* cand0 = candAll + (size_t)w * 4 * CAPK;
    int* mycnt = scnt + w * 4;
    const float4* pts = g_pts4 + (size_t)b * NN;

    float cx[4], cy[4], cz[4];
    int oidx[4];
#pragma unroll
    for (int i = 0; i < 4; i++) {
        float4 c = pts[nbase + i];
        cx[i] = c.x; cy[i] = c.y; cz[i] = c.z;
        oidx[i] = __float_as_int(c.w);
    }

    int xlo = 9, xhi = 0, ylo = 9, yhi = 0, zlo = 9, zhi = 0;
#pragma unroll
    for (int i = 0; i < 4; i++) {
        int cxi = min((int)(cx[i] * 10.f), 9);
        int cyi = min((int)(cy[i] * 10.f), 9);
        int czi = min((int)(cz[i] * 10.f), 9);
        xlo = min(xlo, max(cxi - 2, 0)); xhi = max(xhi, min(cxi + 2, 9));
        ylo = min(ylo, max(cyi - 2, 0)); yhi = max(yhi, min(cyi + 2, 9));
        zlo = min(zlo, max(czi - 2, 0)); zhi = max(zhi, min(czi + 2, 9));
    }

    for (int zz = zlo; zz <= zhi; zz++) {
        for (int yy = ylo; yy <= yhi; yy++) {
            int rb = (zz * 10 + yy) * 10;
            int s = scell[rb + xlo], e = scell[rb + xhi + 1];
            for (int p = s + lane; p < e; p += 32) {
                float4 pt = pts[p];
                unsigned lowbase = ((unsigned)__float_as_int(pt.w) << 12) | (unsigned)p;
#pragma unroll
                for (int i = 0; i < 4; i++) {
                    float dx = pt.x - cx[i], dy = pt.y - cy[i], dz = pt.z - cz[i];
                    float d2 = fmaf(dx, dx, fmaf(dy, dy, dz * dz));
                    if (d2 <= R2C) {
                        int pos = atomicAdd(&mycnt[i], 1);
                        if (pos < CAPK)
                            cand0[i * CAPK + pos] =
                                ((unsigned long long)__float_as_uint(d2) << 32) | lowbase;
                    }
                }
            }
        }
    }
    __syncwarp();

#pragma unroll
    for (int i = 0; i < 4; i++) {
        size_t cg = (size_t)b * NN + oidx[i];
        int M = min(mycnt[i], CAPK);
        unsigned long long* cd = cand0 + i * CAPK;
        unsigned lmask = (1u << lane) - 1u;

        if (lane >= M) {
            g_idx[cg * NS + lane] = oidx[i];
            g_gx[cg * NS + lane] = 0.0f;
            g_gy[cg * NS + lane] = 0.0f;
            g_gz[cg * NS + lane] = 0.0f;
        }

        unsigned long long k[7];
#pragma unroll
        for (int t = 0; t < 7; t++) {
            int p = lane + 32 * t;
            k[t] = (p < M) ? cd[p] : ~0ull;
        }
        unsigned bms[7];
        int Mt = 0;
#pragma unroll
        for (int t = 0; t < 7; t++) {
            bms[t] = __ballot_sync(0xffffffffu, k[t] < TIGHTKEY64);
            Mt += __popc(bms[t]);
        }

        if (Mt >= NS) {
            int base = 0;
#pragma unroll
            for (int t = 0; t < 7; t++) {
                if (k[t] < TIGHTKEY64)
                    cd[base + __popc(bms[t] & lmask)] = k[t];
                base += __popc(bms[t]);
            }
            __syncwarp();
            unsigned long long k2[7];
            int rr[7];
#pragma unroll
            for (int t = 0; t < 7; t++) {
                int p = lane + 32 * t;
                k2[t] = (p < Mt) ? cd[p] : ~0ull;
                rr[t] = 0;
            }
            RANK_LOOP(cd, Mt, k2, rr);
#pragma unroll
            for (int t = 0; t < 7; t++) {
                int p = lane + 32 * t;
                if (p < Mt && rr[t] < NS) {
                    int low = (int)(k2[t] & 0xffffffffull);
                    int jj = (low >> 12) & 0xFFF;
                    float4 p4 = pts[low & 0xFFF];
                    g_idx[cg * NS + rr[t]] = jj;
                    g_gx[cg * NS + rr[t]] = p4.x - cx[i];
                    g_gy[cg * NS + rr[t]] = p4.y - cy[i];
                    g_gz[cg * NS + rr[t]] = p4.z - cz[i];
                }
            }
        } else {
            int rr[7];
#pragma unroll
            for (int t = 0; t < 7; t++) rr[t] = 0;
            RANK_LOOP(cd, M, k, rr);
#pragma unroll
            for (int t = 0; t < 7; t++) {
                int p = lane + 32 * t;
                if (p < M && rr[t] < NS) {
                    int low = (int)(k[t] & 0xffffffffull);
                    int jj = (low >> 12) & 0xFFF;
                    float4 p4 = pts[low & 0xFFF];
                    g_idx[cg * NS + rr[t]] = jj;
                    g_gx[cg * NS + rr[t]] = p4.x - cx[i];
                    g_gy[cg * NS + rr[t]] = p4.y - cy[i];
                    g_gz[cg * NS + rr[t]] = p4.z - cz[i];
                }
            }
        }
        __syncwarp();
    }
}

// ---------------- projgen: MLP + normalize + rank-32 proj (reg-trimmed, 4 CTAs/SM) ----------------
#define CW 2
__global__ __launch_bounds__(256, 4) void projgen_kernel(
    const float* __restrict__ W1, const float* __restrict__ b1,
    const float* __restrict__ W2, const float* __restrict__ b2,
    const float* __restrict__ W3, const float* __restrict__ b3)
{
    __shared__ float swfAll[8][512];
    __shared__ int   snjAll[8][32];
    __shared__ float sW[448];

    int tid = threadIdx.x, w = tid >> 5, lane = tid & 31;
    if (tid < 24)  sW[tid] = W1[tid];
    if (tid < 8)   sW[24 + tid] = b1[tid];
    if (tid < 128) sW[32 + tid] = W2[tid];
    if (tid < 16)  sW[160 + tid] = b2[tid];
    sW[176 + tid] = W3[tid];
    if (tid < 16)  sW[432 + tid] = b3[tid];
    __syncthreads();

    float* swf = swfAll[w];
    int* snj = snjAll[w];

    for (int it = 0; it < CW; it++) {
        size_t cg = (size_t)blockIdx.x * (8 * CW) + w * CW + it;
        int bb = (int)(cg >> 12);

        int   nj = g_idx[cg * NS + lane];
        float gx = g_gx[cg * NS + lane];
        float gy = g_gy[cg * NS + lane];
        float gz = g_gz[cg * NS + lane];

        float h1[8];
#pragma unroll
        for (int o = 0; o < 8; o++)
            h1[o] = leaky(fmaf(sW[o*3+0], gx, fmaf(sW[o*3+1], gy, fmaf(sW[o*3+2], gz, sW[24+o]))));
        float h2[16];
#pragma unroll
        for (int o = 0; o < 16; o++) {
            float a = sW[160 + o];
#pragma unroll
            for (int i = 0; i < 8; i++) a = fmaf(sW[32 + o*8 + i], h1[i], a);
            h2[o] = leaky(a);
        }
        float wv[16], w2sum = 0.0f;
#pragma unroll
        for (int o = 0; o < 16; o++) {
            float a = sW[432 + o];
#pragma unroll
            for (int i = 0; i < 16; i++) a = fmaf(sW[176 + o*16 + i], h2[i], a);
            wv[o] = a; w2sum = fmaf(a, a, w2sum);
        }
        float inv1 = rsqrtf(fmaxf(w2sum, 1e-8f));

        // fused normalize + staged float4 store (no wn[16] array)
        float4* swf4 = (float4*)swf;
        float wq0 = 0.f, wq1 = 0.f, wq2 = 0.f;
#pragma unroll
        for (int kk = 0; kk < 16; kk++) {
            float t = wv[kk] * wv[kk];
#pragma unroll
            for (int off = 16; off; off >>= 1) t += __shfl_xor_sync(0xffffffffu, t, off);
            float s2 = fmaxf(sqrtf(fmaxf(t, 1e-8f)), 1.0f);
            float wn = wv[kk] * inv1 * (1.0f / s2);
            int j = kk & 3;
            if (j == 0) wq0 = wn;
            else if (j == 1) wq1 = wn;
            else if (j == 2) wq2 = wn;
            else swf4[(kk >> 2) * 32 + lane] = make_float4(wq0, wq1, wq2, wn);
        }
        snj[lane] = nj;
        __syncwarp();

        const float* fT = g_featT + (size_t)bb * NN * CC;
        float2 buf[4];
#pragma unroll
        for (int p = 0; p < 4; p++)
            buf[p] = *(const float2*)(fT + (size_t)snj[p] * CC + 2 * lane);

        float acc0[16], acc1[16];
#pragma unroll
        for (int kk = 0; kk < 16; kk++) { acc0[kk] = 0.0f; acc1[kk] = 0.0f; }

#pragma unroll
        for (int s = 0; s < 32; s++) {
            float2 f = buf[s & 3];
            if (s < 28)
                buf[s & 3] = *(const float2*)(fT + (size_t)snj[s + 4] * CC + 2 * lane);
            float4 q0 = swf4[s], q1 = swf4[32 + s], q2 = swf4[64 + s], q3 = swf4[96 + s];
            acc0[0]  = fmaf(q0.x, f.x, acc0[0]);  acc1[0]  = fmaf(q0.x, f.y, acc1[0]);
            acc0[1]  = fmaf(q0.y, f.x, acc0[1]);  acc1[1]  = fmaf(q0.y, f.y, acc1[1]);
            acc0[2]  = fmaf(q0.z, f.x, acc0[2]);  acc1[2]  = fmaf(q0.z, f.y, acc1[2]);
            acc0[3]  = fmaf(q0.w, f.x, acc0[3]);  acc1[3]  = fmaf(q0.w, f.y, acc1[3]);
            acc0[4]  = fmaf(q1.x, f.x, acc0[4]);  acc1[4]  = fmaf(q1.x, f.y, acc1[4]);
            acc0[5]  = fmaf(q1.y, f.x, acc0[5]);  acc1[5]  = fmaf(q1.y, f.y, acc1[5]);
            acc0[6]  = fmaf(q1.z, f.x, acc0[6]);  acc1[6]  = fmaf(q1.z, f.y, acc1[6]);
            acc0[7]  = fmaf(q1.w, f.x, acc0[7]);  acc1[7]  = fmaf(q1.w, f.y, acc1[7]);
            acc0[8]  = fmaf(q2.x, f.x, acc0[8]);  acc1[8]  = fmaf(q2.x, f.y, acc1[8]);
            acc0[9]  = fmaf(q2.y, f.x, acc0[9]);  acc1[9]  = fmaf(q2.y, f.y, acc1[9]);
            acc0[10] = fmaf(q2.z, f.x, acc0[10]); acc1[10] = fmaf(q2.z, f.y, acc1[10]);
            acc0[11] = fmaf(q2.w, f.x, acc0[11]); acc1[11] = fmaf(q2.w, f.y, acc1[11]);
            acc0[12] = fmaf(q3.x, f.x, acc0[12]); acc1[12] = fmaf(q3.x, f.y, acc1[12]);
            acc0[13] = fmaf(q3.y, f.x, acc0[13]); acc1[13] = fmaf(q3.y, f.y, acc1[13]);
            acc0[14] = fmaf(q3.z, f.x, acc0[14]); acc1[14] = fmaf(q3.z, f.y, acc1[14]);
            acc0[15] = fmaf(q3.w, f.x, acc0[15]); acc1[15] = fmaf(q3.w, f.y, acc1[15]);
        }

        uint32_t* row = (uint32_t*)(g_projLb + cg * 2048);
#pragma unroll
        for (int kk = 0; kk < 16; kk++) {
            float v0 = leaky(acc0[kk]), v1 = leaky(acc1[kk]);
            float r0, r1;
            uint32_t hw = pack_hi(v0, v1, r0, r1);
            uint32_t lw = pack_bf2(r0, r1);
            row[kk * 32 + lane] = hw;
            row[512 + kk * 32 + lane] = lw;
        }
        __syncwarp();
    }
}

// ---------------- GEMM (bf16 hi/lo split, m16n8k16) ----------------
#define AW (128 * 20)
#define BW (64 * 20)
#define STGW (2 * AW + 2 * BW)
#define GEMM_SMEM_BYTES (2 * STGW * 4)

__global__ __launch_bounds__(256) void gemm_bf16_kernel(
    const float* __restrict__ bc, float* __restrict__ out)
{
    extern __shared__ uint32_t smw[];
    int tid = threadIdx.x, lane = tid & 31, w = tid >> 5;
    size_t row0 = (size_t)blockIdx.x * 128;
    int b = (int)(row0 >> 12), n0 = (int)(row0 & 4095);

    int ar = tid >> 1, ahalf = tid & 1;
    int br = tid >> 2, bq = tid & 3;

    const uint32_t* rowA = (const uint32_t*)(g_projLb + (row0 + ar) * 2048);
    const uint32_t* rowB = (const uint32_t*)(g_WcPb + (size_t)br * 2048);

    int wi = (w & 3) * 32;
    int wj = (w >> 2) * 32;

    float acc[2][4][4];
#pragma unroll
    for (int i = 0; i < 2; i++)
#pragma unroll
        for (int j = 0; j < 4; j++)
#pragma unroll
            for (int q = 0; q < 4; q++) acc[i][j][q] = 0.0f;

    uint4 aH0, aH1, aL0, aL1, bH, bL;
    {
        const uint4* pAh = (const uint4*)(rowA + ahalf * 8);
        const uint4* pAl = (const uint4*)(rowA + 512 + ahalf * 8);
        aH0 = pAh[0]; aH1 = pAh[1]; aL0 = pAl[0]; aL1 = pAl[1];
        bH = *(const uint4*)(rowB + bq * 4);
        bL = *(const uint4*)(rowB + 512 + bq * 4);
    }
    {
        uint32_t* buf = smw;
        *(uint4*)(buf + ar * 20 + ahalf * 8)          = aH0;
        *(uint4*)(buf + ar * 20 + ahalf * 8 + 4)      = aH1;
        *(uint4*)(buf + AW + ar * 20 + ahalf * 8)     = aL0;
        *(uint4*)(buf + AW + ar * 20 + ahalf * 8 + 4) = aL1;
        *(uint4*)(buf + 2 * AW + br * 20 + bq * 4)          = bH;
        *(uint4*)(buf + 2 * AW + BW + br * 20 + bq * 4)     = bL;
    }
    __syncthreads();

    for (int s = 0; s < 32; s++) {
        if (s + 1 < 32) {
            int wb = (s + 1) * 16;
            const uint4* pAh = (const uint4*)(rowA + wb + ahalf * 8);
            const uint4* pAl = (const uint4*)(rowA + 512 + wb + ahalf * 8);
            aH0 = pAh[0]; aH1 = pAh[1]; aL0 = pAl[0]; aL1 = pAl[1];
            bH = *(const uint4*)(rowB + wb + bq * 4);
            bL = *(const uint4*)(rowB + 512 + wb + bq * 4);
        }
        const uint32_t* buf = smw + (s & 1) * STGW;
        const uint32_t* Ah = buf;
        const uint32_t* Al = buf + AW;
        const uint32_t* Bh = buf + 2 * AW;
        const uint32_t* Bl = buf + 2 * AW + BW;

#pragma unroll
        for (int t = 0; t < 2; t++) {
            int wb = t * 8;
            uint32_t ah[2][4], al[2][4];
#pragma unroll
            for (int ii = 0; ii < 2; ii++) {
                int r = wi + ii * 16 + (lane >> 2);
                int c0 = wb + (lane & 3);
                ah[ii][0] = Ah[r * 20 + c0];
                ah[ii][1] = Ah[(r + 8) * 20 + c0];
                ah[ii][2] = Ah[r * 20 + c0 + 4];
                ah[ii][3] = Ah[(r + 8) * 20 + c0 + 4];
                al[ii][0] = Al[r * 20 + c0];
                al[ii][1] = Al[(r + 8) * 20 + c0];
                al[ii][2] = Al[r * 20 + c0 + 4];
                al[ii][3] = Al[(r + 8) * 20 + c0 + 4];
            }
            uint32_t bh[4][2], bl[4][2];
#pragma unroll
            for (int jj = 0; jj < 4; jj++) {
                int n = wj + jj * 8 + (lane >> 2);
                int c0 = wb + (lane & 3);
                bh[jj][0] = Bh[n * 20 + c0];
                bh[jj][1] = Bh[n * 20 + c0 + 4];
                bl[jj][0] = Bl[n * 20 + c0];
                bl[jj][1] = Bl[n * 20 + c0 + 4];
            }
#pragma unroll
            for (int ii = 0; ii < 2; ii++)
#pragma unroll
                for (int jj = 0; jj < 4; jj++) {
                    mma_bf16(acc[ii][jj], ah[ii], bh[jj]);
                    mma_bf16(acc[ii][jj], ah[ii], bl[jj]);
                    mma_bf16(acc[ii][jj], al[ii], bh[jj]);
                }
        }

        if (s + 1 < 32) {
            uint32_t* nb = smw + ((s + 1) & 1) * STGW;
            *(uint4*)(nb + ar * 20 + ahalf * 8)          = aH0;
            *(uint4*)(nb + ar * 20 + ahalf * 8 + 4)      = aH1;
            *(uint4*)(nb + AW + ar * 20 + ahalf * 8)     = aL0;
            *(uint4*)(nb + AW + ar * 20 + ahalf * 8 + 4) = aL1;
            *(uint4*)(nb + 2 * AW + br * 20 + bq * 4)      = bH;
            *(uint4*)(nb + 2 * AW + BW + br * 20 + bq * 4) = bL;
        }
        __syncthreads();
    }

    float* sO = (float*)smw;
#pragma unroll
    for (int ii = 0; ii < 2; ii++)
#pragma unroll
        for (int jj = 0; jj < 4; jj++) {
            int r = wi + ii * 16 + (lane >> 2);
            int o = wj + jj * 8 + (lane & 3) * 2;
            float b0v = __ldg(&bc[o]), b1v = __ldg(&bc[o + 1]);
            sO[o * 140 + r]           = leaky(acc[ii][jj][0] + b0v);
            sO[(o + 1) * 140 + r]     = leaky(acc[ii][jj][1] + b1v);
            sO[o * 140 + r + 8]       = leaky(acc[ii][jj][2] + b0v);
            sO[(o + 1) * 140 + r + 8] = leaky(acc[ii][jj][3] + b1v);
        }
    __syncthreads();

    int oo = tid >> 2, c4 = (tid & 3) * 4;
    float* orow = out + (size_t)b * (OUTC * NN) + (size_t)oo * NN + n0;
#pragma unroll
    for (int q = 0; q < 8; q++) {
        float4 v = *(float4*)&sO[oo * 140 + c4 + q * 16];
        *(float4*)&orow[c4 + q * 16] = v;
    }
}

extern "C" void kernel_launch(void* const* d_in, const int* in_sizes, int n_in,
                              void* d_out, int out_size) {
    const float* xyz  = (const float*)d_in[0];
    const float* feat = (const float*)d_in[1];
    const float* W1 = (const float*)d_in[2];
    const float* b1 = (const float*)d_in[3];
    const float* W2 = (const float*)d_in[4];
    const float* b2 = (const float*)d_in[5];
    const float* W3 = (const float*)d_in[6];
    const float* b3 = (const float*)d_in[7];
    const float* Wc = (const float*)d_in[8];
    const float* bc = (const float*)d_in[9];

    float* out = (float*)d_out;
    float* out_main = out;
    const int xyz_elems = BB * NN * 3;
    const int out_elems = BB * OUTC * NN;
    if (out_size == xyz_elems + out_elems) {
        cudaMemcpyAsync(out, xyz, (size_t)xyz_elems * sizeof(float), cudaMemcpyDeviceToDevice);
        out_main = out + xyz_elems;
    }

    // ncu captures global launch index 3 -> knn; index order keeps projgen at 4
    transpose_kernel<<<dim3(NN / 32, CC / 32, BB), dim3(32, 8)>>>(feat);      // 0
    wcperm_kernel<<<(OUTC * 512) / 256, 256>>>(Wc);                            // 1
    bin_kernel<<<BB, 1024>>>(xyz);                                             // 2

    cudaFuncSetAttribute(knn_kernel, cudaFuncAttributeMaxDynamicSharedMemorySize, (int)KNN_SMEM);
    knn_kernel<<<dim3(NN / 32, BB), 256, KNN_SMEM>>>();                        // 3

    projgen_kernel<<<(BB * NN) / (8 * CW), 256>>>(W1, b1, W2, b2, W3, b3);     // 4

    cudaFuncSetAttribute(gemm_bf16_kernel, cudaFuncAttributeMaxDynamicSharedMemorySize, GEMM_SMEM_BYTES);
    gemm_bf16_kernel<<<(BB * NN) / 128, 256, GEMM_SMEM_BYTES>>>(bc, out_main); // 5
}